// round 4
// baseline (speedup 1.0000x reference)
#include <cuda_runtime.h>
#include <math.h>

#define NB 16
#define S1 512
#define S2 40
#define DV 1024
#define DT 300
#define DA 256
#define DO 500

// Scratch (static device globals: allocation-free)
__device__ float g_f[NB * S2 * DA];          // f = text @ w2            (16,40,256)
__device__ float g_e[NB * S1 * DA];          // e = video @ w1           (16,512,256)
__device__ float g_g[NB * S1 * 4 * DA];      // tanh(cont)               (16,512,1024)

// ---------------------------------------------------------------------------
// Kernel 1: f[b,t,a] = sum_d text[b,t,d] * w2[d,a]
// grid (16,8): block = (batch, 5 consecutive t rows). 256 threads = a.
// ---------------------------------------------------------------------------
__global__ __launch_bounds__(256) void k_text_proj(const float* __restrict__ text,
                                                   const float* __restrict__ w2) {
    __shared__ float ts[5 * DT];
    int b = blockIdx.x, t0 = blockIdx.y * 5;
    int tid = threadIdx.x;
    for (int i = tid; i < 5 * DT; i += 256)
        ts[i] = text[(b * S2 + t0) * DT + i];
    __syncthreads();

    int a = tid;
    for (int tt = 0; tt < 5; tt++) {
        float acc = 0.f;
        const float* w2p = w2 + a;
        #pragma unroll 4
        for (int d = 0; d < DT; d++)
            acc += ts[tt * DT + d] * w2p[d * DA];
        g_f[(b * S2 + t0 + tt) * DA + a] = acc;
    }
}

// ---------------------------------------------------------------------------
// Kernel 2/4: tiled fp32 GEMM  C[M,N] = A[M,K] @ B[K,N] (+ bias)
// BM=128, BN=64, BK=16, 256 threads, 8x4 per-thread tile.
// M % 128 == 0, K % 16 == 0 guaranteed; N guarded (N=500 case).
// ---------------------------------------------------------------------------
template <bool BIAS>
__global__ __launch_bounds__(256) void k_gemm(const float* __restrict__ A,
                                              const float* __restrict__ Bm,
                                              const float* __restrict__ bias,
                                              float* __restrict__ C,
                                              int M, int N, int K) {
    const int BM = 128, BN = 64, BK = 16;
    __shared__ float As[BK][BM + 4];
    __shared__ float Bs[BK][BN + 4];

    int tid = threadIdx.x;
    int brow = blockIdx.x * BM;
    int bcol = blockIdx.y * BN;

    // compute mapping
    int tm = (tid >> 4) << 3;   // 0..120
    int tn = (tid & 15) << 2;   // 0..60
    // load mapping
    int ra = tid >> 1;          // A row within tile: 0..127
    int ca = (tid & 1) << 3;    // A col offset: 0 or 8
    int kb = tid >> 4;          // B row within tile: 0..15
    int cb = (tid & 15) << 2;   // B col offset: 0..60

    float acc[8][4];
    #pragma unroll
    for (int i = 0; i < 8; i++)
        #pragma unroll
        for (int j = 0; j < 4; j++) acc[i][j] = 0.f;

    const float* Ap = A + (long)(brow + ra) * K + ca;
    int colb = bcol + cb;

    for (int k0 = 0; k0 < K; k0 += BK) {
        float4 a0 = *(const float4*)(Ap + k0);
        float4 a1 = *(const float4*)(Ap + k0 + 4);
        float4 bv;
        if (colb < N) bv = *(const float4*)(Bm + (long)(k0 + kb) * N + colb);
        else          bv = make_float4(0.f, 0.f, 0.f, 0.f);

        As[ca + 0][ra] = a0.x; As[ca + 1][ra] = a0.y;
        As[ca + 2][ra] = a0.z; As[ca + 3][ra] = a0.w;
        As[ca + 4][ra] = a1.x; As[ca + 5][ra] = a1.y;
        As[ca + 6][ra] = a1.z; As[ca + 7][ra] = a1.w;
        *(float4*)&Bs[kb][cb] = bv;
        __syncthreads();

        #pragma unroll
        for (int kk = 0; kk < BK; kk++) {
            float4 av0 = *(const float4*)&As[kk][tm];
            float4 av1 = *(const float4*)&As[kk][tm + 4];
            float4 bb  = *(const float4*)&Bs[kk][tn];
            float am[8] = {av0.x, av0.y, av0.z, av0.w, av1.x, av1.y, av1.z, av1.w};
            float bn_[4] = {bb.x, bb.y, bb.z, bb.w};
            #pragma unroll
            for (int i = 0; i < 8; i++)
                #pragma unroll
                for (int j = 0; j < 4; j++)
                    acc[i][j] += am[i] * bn_[j];
        }
        __syncthreads();
    }

    #pragma unroll
    for (int i = 0; i < 8; i++) {
        long row = brow + tm + i;
        #pragma unroll
        for (int j = 0; j < 4; j++) {
            int col = bcol + tn + j;
            if (col < N)
                C[row * N + col] = acc[i][j] + (BIAS ? bias[col] : 0.f);
        }
    }
}

// ---------------------------------------------------------------------------
// Kernel 3: fused attention per (b, 32-row s1 tile).
// fb = f + bias resident in SMEM (40x256). Per row:
//   logits[t] = sum_a tanh(e[a] + fb[t][a]) * w3[a]     (warp t-slices)
//   softmax over t (exact, max-subtracted)
//   text_attn[a] = (sum_t exp_t * fb[t][a]) * inv - bias[a]   (uses sum p = 1)
//   g = tanh([e, ta, e*ta, e-ta]) -> g_g
// ---------------------------------------------------------------------------
__global__ __launch_bounds__(256) void k_attn(const float* __restrict__ w3,
                                              const float* __restrict__ bias) {
    __shared__ float fb[S2 * DA];   // 40 KB
    __shared__ float es[DA];
    __shared__ float w3s[DA];
    __shared__ float bs[DA];
    __shared__ float sc[S2];
    __shared__ float red[2];

    int tid = threadIdx.x;
    int b = blockIdx.x, s0 = blockIdx.y * 32;
    int warp = tid >> 5, lane = tid & 31;

    w3s[tid] = w3[tid];
    bs[tid]  = bias[tid];
    __syncthreads();
    for (int i = tid; i < S2 * DA; i += 256)
        fb[i] = g_f[b * S2 * DA + i] + bs[i & (DA - 1)];

    for (int r = 0; r < 32; r++) {
        int s = s0 + r;
        __syncthreads();                       // guards prev-row readers + fb fill
        es[tid] = g_e[((long)b * S1 + s) * DA + tid];
        __syncthreads();

        // stage 1: logits
        #pragma unroll
        for (int tt = 0; tt < 5; tt++) {
            int t = warp + 8 * tt;
            float p = 0.f;
            #pragma unroll
            for (int j = 0; j < 8; j++) {
                int a = lane + 32 * j;
                p += tanhf(es[a] + fb[t * DA + a]) * w3s[a];
            }
            #pragma unroll
            for (int off = 16; off; off >>= 1)
                p += __shfl_xor_sync(0xffffffffu, p, off);
            if (lane == 0) sc[t] = p;
        }
        __syncthreads();

        // stage 2: softmax stats
        if (tid == 0) {
            float m = sc[0];
            for (int t = 1; t < S2; t++) m = fmaxf(m, sc[t]);
            red[0] = m;
        }
        __syncthreads();
        if (tid < S2) sc[tid] = expf(sc[tid] - red[0]);
        __syncthreads();
        if (tid == 0) {
            float su = 0.f;
            for (int t = 0; t < S2; t++) su += sc[t];
            red[1] = 1.f / su;
        }
        __syncthreads();

        // stage 3+4: text_attn + features
        float acc = 0.f;
        #pragma unroll 8
        for (int t = 0; t < S2; t++)
            acc += sc[t] * fb[t * DA + tid];
        float ta = acc * red[1] - bs[tid];
        float ev = es[tid];

        float* gp = g_g + ((long)b * S1 + s) * (4 * DA) + tid;
        gp[0]        = tanhf(ev);
        gp[DA]       = tanhf(ta);
        gp[2 * DA]   = tanhf(ev * ta);
        gp[3 * DA]   = tanhf(ev - ta);
    }
}

// ---------------------------------------------------------------------------
extern "C" void kernel_launch(void* const* d_in, const int* in_sizes, int n_in,
                              void* d_out, int out_size) {
    const float* video = (const float*)d_in[0];
    const float* text  = (const float*)d_in[1];
    const float* w1    = (const float*)d_in[2];
    const float* w2    = (const float*)d_in[3];
    const float* w3    = (const float*)d_in[4];
    const float* bias  = (const float*)d_in[5];
    const float* w4    = (const float*)d_in[6];
    const float* b4    = (const float*)d_in[7];
    float* out = (float*)d_out;

    float *pe, *pg;
    cudaGetSymbolAddress((void**)&pe, g_e);
    cudaGetSymbolAddress((void**)&pg, g_g);

    // f = text @ w2
    k_text_proj<<<dim3(NB, 8), 256>>>(text, w2);
    // e = video @ w1   (8192 x 1024 @ 1024 x 256)
    k_gemm<false><<<dim3((NB * S1) / 128, DA / 64), 256>>>(video, w1, nullptr, pe,
                                                           NB * S1, DA, DV);
    // fused attention -> g = tanh(cont)
    k_attn<<<dim3(NB, S1 / 32), 256>>>(w3, bias);
    // out = g @ w4 + b4  (8192 x 1024 @ 1024 x 500)
    k_gemm<true><<<dim3((NB * S1) / 128, (DO + 63) / 64), 256>>>(pg, w4, b4, out,
                                                                 NB * S1, DO, 4 * DA);
}

// round 7
// speedup vs baseline: 1.5838x; 1.5838x over previous
#include <cuda_runtime.h>
#include <cuda_bf16.h>
#include <math.h>
#include <cstdint>

#define NB 16
#define S1 512
#define S2 40
#define DV 1024
#define DT 300
#define DA 256
#define DO 500
#define DO_PAD 512

// ---------------------------------------------------------------------------
// Scratch (static device globals: allocation-free)
// ---------------------------------------------------------------------------
__device__ float g_f[NB * S2 * DA];                    // f = text @ w2    (16,40,256)
__device__ float g_e[NB * S1 * DA];                    // e = video @ w1   (16,512,256)
__device__ __nv_bfloat16 g_vh[NB * S1 * DV];           // video split hi
__device__ __nv_bfloat16 g_vl[NB * S1 * DV];           // video split lo
__device__ __nv_bfloat16 g_gh[NB * S1 * 4 * DA];       // tanh(cont) split hi
__device__ __nv_bfloat16 g_gl[NB * S1 * 4 * DA];       // tanh(cont) split lo
__device__ __nv_bfloat16 g_w1h[DA * DV];               // w1^T hi [256,1024]
__device__ __nv_bfloat16 g_w1l[DA * DV];               // w1^T lo
__device__ __nv_bfloat16 g_w4h[DO_PAD * (4 * DA)];     // w4^T hi [512,1024] (rows>=500 zero)
__device__ __nv_bfloat16 g_w4l[DO_PAD * (4 * DA)];     // w4^T lo

// ---------------------------------------------------------------------------
// Fast accurate tanh: 2 MUFU + ~5 ALU, rel err ~1e-6
// ---------------------------------------------------------------------------
__device__ __forceinline__ float fast_tanh(float x) {
    float ax = fabsf(x);
    float e = __expf(-2.f * ax);
    float t = __fdividef(1.f - e, 1.f + e);
    return copysignf(t, x);
}

// mma.sync m16n8k16 bf16 (sm_80+ base feature; NOT arch-specific)
#define MMA16816(c, a0, a1, a2, a3, b0, b1)                                  \
    asm volatile(                                                            \
        "mma.sync.aligned.m16n8k16.row.col.f32.bf16.bf16.f32 "               \
        "{%0,%1,%2,%3}, {%4,%5,%6,%7}, {%8,%9}, {%0,%1,%2,%3};"              \
        : "+f"((c)[0]), "+f"((c)[1]), "+f"((c)[2]), "+f"((c)[3])             \
        : "r"(a0), "r"(a1), "r"(a2), "r"(a3), "r"(b0), "r"(b1))

// ---------------------------------------------------------------------------
// k_prep: out[n*K + k] = split(W[k*N_src + n]); rows n >= N_src zeroed.
// ---------------------------------------------------------------------------
__global__ __launch_bounds__(256) void k_prep(const float* __restrict__ W,
                                              __nv_bfloat16* __restrict__ Oh,
                                              __nv_bfloat16* __restrict__ Ol,
                                              int N_src, int N_pad, int K) {
    int idx = blockIdx.x * 256 + threadIdx.x;
    if (idx >= N_pad * K) return;
    int n = idx / K, k = idx - n * K;
    float v = (n < N_src) ? W[(long)k * N_src + n] : 0.f;
    __nv_bfloat16 h = __float2bfloat16(v);
    __nv_bfloat16 l = __float2bfloat16(v - __bfloat162float(h));
    Oh[idx] = h;
    Ol[idx] = l;
}

// ---------------------------------------------------------------------------
// k_split: row-major fp32 -> hi/lo bf16 (vectorized x4); n % 4 == 0.
// ---------------------------------------------------------------------------
__global__ __launch_bounds__(256) void k_split(const float* __restrict__ X,
                                               __nv_bfloat16* __restrict__ H,
                                               __nv_bfloat16* __restrict__ L,
                                               int n4) {
    int i = blockIdx.x * 256 + threadIdx.x;
    if (i >= n4) return;
    float4 v = ((const float4*)X)[i];
    __nv_bfloat16 h0 = __float2bfloat16(v.x), h1 = __float2bfloat16(v.y);
    __nv_bfloat16 h2 = __float2bfloat16(v.z), h3 = __float2bfloat16(v.w);
    __nv_bfloat16 hh[4] = {h0, h1, h2, h3};
    __nv_bfloat16 ll[4] = {__float2bfloat16(v.x - __bfloat162float(h0)),
                           __float2bfloat16(v.y - __bfloat162float(h1)),
                           __float2bfloat16(v.z - __bfloat162float(h2)),
                           __float2bfloat16(v.w - __bfloat162float(h3))};
    *(uint2*)&H[4 * i] = *(uint2*)hh;
    *(uint2*)&L[4 * i] = *(uint2*)ll;
}

// ---------------------------------------------------------------------------
// Tensor-core GEMM via mma.sync: C[M,N] = A @ Bt^T (+bias), split-bf16.
// A: [M,K] hi/lo bf16 row-major. Bt: [Npad,K] hi/lo bf16 row-major.
// CTA 128x128, BK=32, 8 warps in 2(M)x4(N), 4x4 m16n8k16 tiles per warp.
// ---------------------------------------------------------------------------
#define PITCH 40   // bf16 units per smem row (32 + 8 pad)

__global__ __launch_bounds__(256) void k_gemm_mma(
    const __nv_bfloat16* __restrict__ Ah, const __nv_bfloat16* __restrict__ Al,
    const __nv_bfloat16* __restrict__ Bh, const __nv_bfloat16* __restrict__ Bl,
    const float* __restrict__ bias, float* __restrict__ C, int N, int K) {
    __shared__ __nv_bfloat16 sAh[128 * PITCH];
    __shared__ __nv_bfloat16 sAl[128 * PITCH];
    __shared__ __nv_bfloat16 sBh[128 * PITCH];
    __shared__ __nv_bfloat16 sBl[128 * PITCH];

    int tid = threadIdx.x, lane = tid & 31, wid = tid >> 5;
    int g = lane >> 2, tg = lane & 3;
    int brow = blockIdx.x * 128, bn = blockIdx.y * 128;
    int wm = (wid >> 2) * 64, wn = (wid & 3) * 32;

    float acc[4][4][4];
    #pragma unroll
    for (int mi = 0; mi < 4; mi++)
        #pragma unroll
        for (int ni = 0; ni < 4; ni++)
            #pragma unroll
            for (int q = 0; q < 4; q++) acc[mi][ni][q] = 0.f;

    int lrow = tid >> 2;   // 0..63 (iter 0), +64 (iter 1)
    int lseg = tid & 3;    // 8-bf16 segment within the 32-wide chunk

    for (int kc = 0; kc < K; kc += 32) {
        #pragma unroll
        for (int it = 0; it < 2; it++) {
            int r = it * 64 + lrow;
            int c = kc + lseg * 8;
            long ga = (long)(brow + r) * K + c;
            long gb = (long)(bn + r) * K + c;
            int so = r * PITCH + lseg * 8;
            *(uint4*)&sAh[so] = *(const uint4*)&Ah[ga];
            *(uint4*)&sAl[so] = *(const uint4*)&Al[ga];
            *(uint4*)&sBh[so] = *(const uint4*)&Bh[gb];
            *(uint4*)&sBl[so] = *(const uint4*)&Bl[gb];
        }
        __syncthreads();

        #pragma unroll
        for (int ks = 0; ks < 2; ks++) {
            int kb = ks * 16 + 2 * tg;
            // B fragments (kept live across mi)
            uint32_t bh0[4], bh1[4], bl0[4], bl1[4];
            #pragma unroll
            for (int ni = 0; ni < 4; ni++) {
                int br = (wn + ni * 8 + g) * PITCH;
                bh0[ni] = *(const uint32_t*)&sBh[br + kb];
                bh1[ni] = *(const uint32_t*)&sBh[br + kb + 8];
                bl0[ni] = *(const uint32_t*)&sBl[br + kb];
                bl1[ni] = *(const uint32_t*)&sBl[br + kb + 8];
            }
            #pragma unroll
            for (int mi = 0; mi < 4; mi++) {
                int ar0 = (wm + mi * 16 + g) * PITCH;
                int ar1 = ar0 + 8 * PITCH;
                uint32_t ah0 = *(const uint32_t*)&sAh[ar0 + kb];
                uint32_t ah1 = *(const uint32_t*)&sAh[ar1 + kb];
                uint32_t ah2 = *(const uint32_t*)&sAh[ar0 + kb + 8];
                uint32_t ah3 = *(const uint32_t*)&sAh[ar1 + kb + 8];
                uint32_t al0 = *(const uint32_t*)&sAl[ar0 + kb];
                uint32_t al1 = *(const uint32_t*)&sAl[ar1 + kb];
                uint32_t al2 = *(const uint32_t*)&sAl[ar0 + kb + 8];
                uint32_t al3 = *(const uint32_t*)&sAl[ar1 + kb + 8];
                #pragma unroll
                for (int ni = 0; ni < 4; ni++) {
                    MMA16816(acc[mi][ni], ah0, ah1, ah2, ah3, bh0[ni], bh1[ni]);
                    MMA16816(acc[mi][ni], ah0, ah1, ah2, ah3, bl0[ni], bl1[ni]);
                    MMA16816(acc[mi][ni], al0, al1, al2, al3, bh0[ni], bh1[ni]);
                }
            }
        }
        __syncthreads();
    }

    // epilogue: c0,c1 -> (row, col..col+1); c2,c3 -> (row+8, ...)
    #pragma unroll
    for (int mi = 0; mi < 4; mi++) {
        int row = brow + wm + mi * 16 + g;
        #pragma unroll
        for (int ni = 0; ni < 4; ni++) {
            int col = bn + wn + ni * 8 + 2 * tg;
            if (col < N) {
                float b0 = bias ? bias[col] : 0.f;
                float b1 = bias ? bias[col + 1] : 0.f;
                *(float2*)&C[(long)row * N + col] =
                    make_float2(acc[mi][ni][0] + b0, acc[mi][ni][1] + b1);
                *(float2*)&C[(long)(row + 8) * N + col] =
                    make_float2(acc[mi][ni][2] + b0, acc[mi][ni][3] + b1);
            }
        }
    }
}

// ---------------------------------------------------------------------------
// k_text_proj: f[b,t,a] = sum_d text[b,t,d] * w2[d,a]
// ---------------------------------------------------------------------------
__global__ __launch_bounds__(256) void k_text_proj(const float* __restrict__ text,
                                                   const float* __restrict__ w2) {
    __shared__ float ts[5 * DT];
    int b = blockIdx.x, t0 = blockIdx.y * 5;
    int tid = threadIdx.x;
    for (int i = tid; i < 5 * DT; i += 256)
        ts[i] = text[(b * S2 + t0) * DT + i];
    __syncthreads();

    int a = tid;
    for (int tt = 0; tt < 5; tt++) {
        float acc = 0.f;
        const float* w2p = w2 + a;
        #pragma unroll 4
        for (int d = 0; d < DT; d++)
            acc += ts[tt * DT + d] * w2p[d * DA];
        g_f[(b * S2 + t0 + tt) * DA + a] = acc;
    }
}

// ---------------------------------------------------------------------------
// k_attn: fused attention; writes tanh(cont) split to g_gh/g_gl.
// ---------------------------------------------------------------------------
__global__ __launch_bounds__(256) void k_attn(const float* __restrict__ w3,
                                              const float* __restrict__ bias) {
    __shared__ float fb[S2 * DA];
    __shared__ float es[DA];
    __shared__ float w3s[DA];
    __shared__ float bs[DA];
    __shared__ float sc[S2];
    __shared__ float red[2];

    int tid = threadIdx.x;
    int b = blockIdx.x, s0 = blockIdx.y * 32;
    int warp = tid >> 5, lane = tid & 31;

    w3s[tid] = w3[tid];
    bs[tid] = bias[tid];
    __syncthreads();
    for (int i = tid; i < S2 * DA; i += 256)
        fb[i] = g_f[b * S2 * DA + i] + bs[i & (DA - 1)];

    for (int r = 0; r < 32; r++) {
        int s = s0 + r;
        __syncthreads();
        es[tid] = g_e[((long)b * S1 + s) * DA + tid];
        __syncthreads();

        #pragma unroll
        for (int tt = 0; tt < 5; tt++) {
            int t = warp + 8 * tt;
            float p = 0.f;
            #pragma unroll
            for (int j = 0; j < 8; j++) {
                int a = lane + 32 * j;
                p += fast_tanh(es[a] + fb[t * DA + a]) * w3s[a];
            }
            #pragma unroll
            for (int off = 16; off; off >>= 1)
                p += __shfl_xor_sync(0xffffffffu, p, off);
            if (lane == 0) sc[t] = p;
        }
        __syncthreads();

        if (tid == 0) {
            float m = sc[0];
            for (int t = 1; t < S2; t++) m = fmaxf(m, sc[t]);
            red[0] = m;
        }
        __syncthreads();
        if (tid < S2) sc[tid] = expf(sc[tid] - red[0]);
        __syncthreads();
        if (tid == 0) {
            float su = 0.f;
            for (int t = 0; t < S2; t++) su += sc[t];
            red[1] = 1.f / su;
        }
        __syncthreads();

        float acc = 0.f;
        #pragma unroll 8
        for (int t = 0; t < S2; t++)
            acc += sc[t] * fb[t * DA + tid];
        float ta = acc * red[1] - bs[tid];
        float ev = es[tid];

        long go = ((long)b * S1 + s) * (4 * DA) + tid;
        float vals[4] = {fast_tanh(ev), fast_tanh(ta),
                         fast_tanh(ev * ta), fast_tanh(ev - ta)};
        #pragma unroll
        for (int q = 0; q < 4; q++) {
            __nv_bfloat16 h = __float2bfloat16(vals[q]);
            g_gh[go + q * DA] = h;
            g_gl[go + q * DA] = __float2bfloat16(vals[q] - __bfloat162float(h));
        }
    }
}

// ---------------------------------------------------------------------------
extern "C" void kernel_launch(void* const* d_in, const int* in_sizes, int n_in,
                              void* d_out, int out_size) {
    const float* video = (const float*)d_in[0];
    const float* text  = (const float*)d_in[1];
    const float* w1    = (const float*)d_in[2];
    const float* w2    = (const float*)d_in[3];
    const float* w3    = (const float*)d_in[4];
    const float* bias  = (const float*)d_in[5];
    const float* w4    = (const float*)d_in[6];
    const float* b4    = (const float*)d_in[7];
    float* out = (float*)d_out;

    float* pe;
    __nv_bfloat16 *pvh, *pvl, *pgh, *pgl, *p1h, *p1l, *p4h, *p4l;
    cudaGetSymbolAddress((void**)&pe, g_e);
    cudaGetSymbolAddress((void**)&pvh, g_vh);
    cudaGetSymbolAddress((void**)&pvl, g_vl);
    cudaGetSymbolAddress((void**)&pgh, g_gh);
    cudaGetSymbolAddress((void**)&pgl, g_gl);
    cudaGetSymbolAddress((void**)&p1h, g_w1h);
    cudaGetSymbolAddress((void**)&p1l, g_w1l);
    cudaGetSymbolAddress((void**)&p4h, g_w4h);
    cudaGetSymbolAddress((void**)&p4l, g_w4l);

    // weight prep (transpose + split bf16)
    k_prep<<<(DA * DV + 255) / 256, 256>>>(w1, p1h, p1l, DA, DA, DV);
    k_prep<<<(DO_PAD * 4 * DA + 255) / 256, 256>>>(w4, p4h, p4l, DO, DO_PAD, 4 * DA);
    // video split to hi/lo bf16
    int v4 = NB * S1 * DV / 4;
    k_split<<<(v4 + 255) / 256, 256>>>(video, pvh, pvl, v4);
    // f = text @ w2
    k_text_proj<<<dim3(NB, 8), 256>>>(text, w2);
    // e = video @ w1  (8192x256, K=1024) — mma.sync split-bf16
    k_gemm_mma<<<dim3((NB * S1) / 128, DA / 128), 256>>>(
        pvh, pvl, p1h, p1l, nullptr, pe, DA, DV);
    // fused attention -> g (split bf16)
    k_attn<<<dim3(NB, S1 / 32), 256>>>(w3, bias);
    // out = g @ w4 + b4  (8192x500, K=1024) — mma.sync split-bf16
    k_gemm_mma<<<dim3((NB * S1) / 128, DO_PAD / 128), 256>>>(
        pgh, pgl, p4h, p4l, b4, out, DO, 4 * DA);
}

// round 8
// speedup vs baseline: 2.7633x; 1.7448x over previous
#include <cuda_runtime.h>
#include <cuda_bf16.h>
#include <math.h>
#include <cstdint>

#define NB 16
#define S1 512
#define S2 40
#define DV 1024
#define DT 300
#define DA 256
#define DO 500
#define DO_PAD 512

// ---------------------------------------------------------------------------
// Scratch (static device globals: allocation-free)
// ---------------------------------------------------------------------------
__device__ float g_f[NB * S2 * DA];                    // f = text @ w2    (16,40,256)
__device__ float g_e[NB * S1 * DA];                    // e = video @ w1   (16,512,256)
__device__ __nv_bfloat16 g_vh[NB * S1 * DV];           // video split hi
__device__ __nv_bfloat16 g_vl[NB * S1 * DV];           // video split lo
__device__ __nv_bfloat16 g_gh[NB * S1 * 4 * DA];       // tanh(cont) split hi
__device__ __nv_bfloat16 g_gl[NB * S1 * 4 * DA];       // tanh(cont) split lo
__device__ __nv_bfloat16 g_w1h[DA * DV];               // w1^T hi [256,1024]
__device__ __nv_bfloat16 g_w1l[DA * DV];               // w1^T lo
__device__ __nv_bfloat16 g_w4h[DO_PAD * (4 * DA)];     // w4^T hi [512,1024] (rows>=500 zero)
__device__ __nv_bfloat16 g_w4l[DO_PAD * (4 * DA)];     // w4^T lo

// ---------------------------------------------------------------------------
// Fast accurate tanh: 2 MUFU + ~5 ALU, rel err ~1e-6
// ---------------------------------------------------------------------------
__device__ __forceinline__ float fast_tanh(float x) {
    float ax = fabsf(x);
    float e = __expf(-2.f * ax);
    float t = __fdividef(1.f - e, 1.f + e);
    return copysignf(t, x);
}

// mma.sync m16n8k16 bf16 (sm_80+ base feature; NOT arch-specific)
#define MMA16816(c, a0, a1, a2, a3, b0, b1)                                  \
    asm volatile(                                                            \
        "mma.sync.aligned.m16n8k16.row.col.f32.bf16.bf16.f32 "               \
        "{%0,%1,%2,%3}, {%4,%5,%6,%7}, {%8,%9}, {%0,%1,%2,%3};"              \
        : "+f"((c)[0]), "+f"((c)[1]), "+f"((c)[2]), "+f"((c)[3])             \
        : "r"(a0), "r"(a1), "r"(a2), "r"(a3), "r"(b0), "r"(b1))

// ---------------------------------------------------------------------------
// k_prep: out[n*K + k] = split(W[k*N_src + n]); rows n >= N_src zeroed.
// ---------------------------------------------------------------------------
__global__ __launch_bounds__(256) void k_prep(const float* __restrict__ W,
                                              __nv_bfloat16* __restrict__ Oh,
                                              __nv_bfloat16* __restrict__ Ol,
                                              int N_src, int N_pad, int K) {
    int idx = blockIdx.x * 256 + threadIdx.x;
    if (idx >= N_pad * K) return;
    int n = idx / K, k = idx - n * K;
    float v = (n < N_src) ? W[(long)k * N_src + n] : 0.f;
    __nv_bfloat16 h = __float2bfloat16(v);
    __nv_bfloat16 l = __float2bfloat16(v - __bfloat162float(h));
    Oh[idx] = h;
    Ol[idx] = l;
}

// ---------------------------------------------------------------------------
// k_split: row-major fp32 -> hi/lo bf16 (vectorized x4); n % 4 == 0.
// ---------------------------------------------------------------------------
__global__ __launch_bounds__(256) void k_split(const float* __restrict__ X,
                                               __nv_bfloat16* __restrict__ H,
                                               __nv_bfloat16* __restrict__ L,
                                               int n4) {
    int i = blockIdx.x * 256 + threadIdx.x;
    if (i >= n4) return;
    float4 v = ((const float4*)X)[i];
    __nv_bfloat16 h0 = __float2bfloat16(v.x), h1 = __float2bfloat16(v.y);
    __nv_bfloat16 h2 = __float2bfloat16(v.z), h3 = __float2bfloat16(v.w);
    __nv_bfloat16 hh[4] = {h0, h1, h2, h3};
    __nv_bfloat16 ll[4] = {__float2bfloat16(v.x - __bfloat162float(h0)),
                           __float2bfloat16(v.y - __bfloat162float(h1)),
                           __float2bfloat16(v.z - __bfloat162float(h2)),
                           __float2bfloat16(v.w - __bfloat162float(h3))};
    *(uint2*)&H[4 * i] = *(uint2*)hh;
    *(uint2*)&L[4 * i] = *(uint2*)ll;
}

// ---------------------------------------------------------------------------
// Tensor-core GEMM via mma.sync: C[M,N] = A @ Bt^T (+bias), split-bf16.
// A: [M,K] hi/lo bf16 row-major. Bt: [Npad,K] hi/lo bf16 row-major.
// CTA 128x128, BK=32, 8 warps in 2(M)x4(N), 4x4 m16n8k16 tiles per warp.
// Register-prefetch pipeline: next chunk's LDGs issued before MMA phase.
// ---------------------------------------------------------------------------
#define PITCH 40   // bf16 units per smem row (32 + 8 pad)

__global__ __launch_bounds__(256) void k_gemm_mma(
    const __nv_bfloat16* __restrict__ Ah, const __nv_bfloat16* __restrict__ Al,
    const __nv_bfloat16* __restrict__ Bh, const __nv_bfloat16* __restrict__ Bl,
    const float* __restrict__ bias, float* __restrict__ C, int N, int K) {
    __shared__ __nv_bfloat16 sAh[128 * PITCH];
    __shared__ __nv_bfloat16 sAl[128 * PITCH];
    __shared__ __nv_bfloat16 sBh[128 * PITCH];
    __shared__ __nv_bfloat16 sBl[128 * PITCH];

    int tid = threadIdx.x, lane = tid & 31, wid = tid >> 5;
    int g = lane >> 2, tg = lane & 3;
    int brow = blockIdx.x * 128, bn = blockIdx.y * 128;
    int wm = (wid >> 2) * 64, wn = (wid & 3) * 32;

    float acc[4][4][4];
    #pragma unroll
    for (int mi = 0; mi < 4; mi++)
        #pragma unroll
        for (int ni = 0; ni < 4; ni++)
            #pragma unroll
            for (int q = 0; q < 4; q++) acc[mi][ni][q] = 0.f;

    int lrow = tid >> 2;   // 0..63 (iter 0), +64 (iter 1)
    int lseg = tid & 3;    // 8-bf16 segment within the 32-wide chunk

    uint4 ra_h[2], ra_l[2], rb_h[2], rb_l[2];

    // prefetch chunk 0
    #pragma unroll
    for (int it = 0; it < 2; it++) {
        int r = it * 64 + lrow;
        int c = lseg * 8;
        long ga = (long)(brow + r) * K + c;
        long gb = (long)(bn + r) * K + c;
        ra_h[it] = *(const uint4*)&Ah[ga];
        ra_l[it] = *(const uint4*)&Al[ga];
        rb_h[it] = *(const uint4*)&Bh[gb];
        rb_l[it] = *(const uint4*)&Bl[gb];
    }

    for (int kc = 0; kc < K; kc += 32) {
        // store current chunk to smem
        #pragma unroll
        for (int it = 0; it < 2; it++) {
            int so = (it * 64 + lrow) * PITCH + lseg * 8;
            *(uint4*)&sAh[so] = ra_h[it];
            *(uint4*)&sAl[so] = ra_l[it];
            *(uint4*)&sBh[so] = rb_h[it];
            *(uint4*)&sBl[so] = rb_l[it];
        }
        __syncthreads();

        // issue next chunk's LDGs early (overlap with MMA phase)
        if (kc + 32 < K) {
            #pragma unroll
            for (int it = 0; it < 2; it++) {
                int r = it * 64 + lrow;
                int c = kc + 32 + lseg * 8;
                long ga = (long)(brow + r) * K + c;
                long gb = (long)(bn + r) * K + c;
                ra_h[it] = *(const uint4*)&Ah[ga];
                ra_l[it] = *(const uint4*)&Al[ga];
                rb_h[it] = *(const uint4*)&Bh[gb];
                rb_l[it] = *(const uint4*)&Bl[gb];
            }
        }

        #pragma unroll
        for (int ks = 0; ks < 2; ks++) {
            int kb = ks * 16 + 2 * tg;
            // B fragments (kept live across mi)
            uint32_t bh0[4], bh1[4], bl0[4], bl1[4];
            #pragma unroll
            for (int ni = 0; ni < 4; ni++) {
                int br = (wn + ni * 8 + g) * PITCH;
                bh0[ni] = *(const uint32_t*)&sBh[br + kb];
                bh1[ni] = *(const uint32_t*)&sBh[br + kb + 8];
                bl0[ni] = *(const uint32_t*)&sBl[br + kb];
                bl1[ni] = *(const uint32_t*)&sBl[br + kb + 8];
            }
            #pragma unroll
            for (int mi = 0; mi < 4; mi++) {
                int ar0 = (wm + mi * 16 + g) * PITCH;
                int ar1 = ar0 + 8 * PITCH;
                uint32_t ah0 = *(const uint32_t*)&sAh[ar0 + kb];
                uint32_t ah1 = *(const uint32_t*)&sAh[ar1 + kb];
                uint32_t ah2 = *(const uint32_t*)&sAh[ar0 + kb + 8];
                uint32_t ah3 = *(const uint32_t*)&sAh[ar1 + kb + 8];
                uint32_t al0 = *(const uint32_t*)&sAl[ar0 + kb];
                uint32_t al1 = *(const uint32_t*)&sAl[ar1 + kb];
                uint32_t al2 = *(const uint32_t*)&sAl[ar0 + kb + 8];
                uint32_t al3 = *(const uint32_t*)&sAl[ar1 + kb + 8];
                #pragma unroll
                for (int ni = 0; ni < 4; ni++) {
                    MMA16816(acc[mi][ni], ah0, ah1, ah2, ah3, bh0[ni], bh1[ni]);
                    MMA16816(acc[mi][ni], ah0, ah1, ah2, ah3, bl0[ni], bl1[ni]);
                    MMA16816(acc[mi][ni], al0, al1, al2, al3, bh0[ni], bh1[ni]);
                }
            }
        }
        __syncthreads();
    }

    // epilogue: c0,c1 -> (row, col..col+1); c2,c3 -> (row+8, ...)
    #pragma unroll
    for (int mi = 0; mi < 4; mi++) {
        int row = brow + wm + mi * 16 + g;
        #pragma unroll
        for (int ni = 0; ni < 4; ni++) {
            int col = bn + wn + ni * 8 + 2 * tg;
            if (col < N) {
                float b0 = bias ? bias[col] : 0.f;
                float b1 = bias ? bias[col + 1] : 0.f;
                *(float2*)&C[(long)row * N + col] =
                    make_float2(acc[mi][ni][0] + b0, acc[mi][ni][1] + b1);
                *(float2*)&C[(long)(row + 8) * N + col] =
                    make_float2(acc[mi][ni][2] + b0, acc[mi][ni][3] + b1);
            }
        }
    }
}

// ---------------------------------------------------------------------------
// k_text_proj: f[b,t,a] = sum_d text[b,t,d] * w2[d,a]
// One (b,t) row per block: grid 640, coalesced w2 reads, high MLP.
// ---------------------------------------------------------------------------
__global__ __launch_bounds__(256) void k_text_proj(const float* __restrict__ text,
                                                   const float* __restrict__ w2) {
    __shared__ float ts[DT];
    int b = blockIdx.x, t = blockIdx.y;
    int tid = threadIdx.x;
    for (int i = tid; i < DT; i += 256)
        ts[i] = text[(b * S2 + t) * DT + i];
    __syncthreads();

    float acc = 0.f;
    const float* w2p = w2 + tid;
    #pragma unroll 4
    for (int d = 0; d < DT; d++)
        acc += ts[d] * w2p[d * DA];
    g_f[(b * S2 + t) * DA + tid] = acc;
}

// ---------------------------------------------------------------------------
// k_attn: fused attention; writes tanh(cont) split to g_gh/g_gl.
// ---------------------------------------------------------------------------
__global__ __launch_bounds__(256) void k_attn(const float* __restrict__ w3,
                                              const float* __restrict__ bias) {
    __shared__ float fb[S2 * DA];
    __shared__ float es[DA];
    __shared__ float w3s[DA];
    __shared__ float bs[DA];
    __shared__ float sc[S2];
    __shared__ float red[2];

    int tid = threadIdx.x;
    int b = blockIdx.x, s0 = blockIdx.y * 32;
    int warp = tid >> 5, lane = tid & 31;

    w3s[tid] = w3[tid];
    bs[tid] = bias[tid];
    __syncthreads();
    for (int i = tid; i < S2 * DA; i += 256)
        fb[i] = g_f[b * S2 * DA + i] + bs[i & (DA - 1)];

    for (int r = 0; r < 32; r++) {
        int s = s0 + r;
        __syncthreads();
        es[tid] = g_e[((long)b * S1 + s) * DA + tid];
        __syncthreads();

        #pragma unroll
        for (int tt = 0; tt < 5; tt++) {
            int t = warp + 8 * tt;
            float p = 0.f;
            #pragma unroll
            for (int j = 0; j < 8; j++) {
                int a = lane + 32 * j;
                p += fast_tanh(es[a] + fb[t * DA + a]) * w3s[a];
            }
            #pragma unroll
            for (int off = 16; off; off >>= 1)
                p += __shfl_xor_sync(0xffffffffu, p, off);
            if (lane == 0) sc[t] = p;
        }
        __syncthreads();

        if (tid == 0) {
            float m = sc[0];
            for (int t = 1; t < S2; t++) m = fmaxf(m, sc[t]);
            red[0] = m;
        }
        __syncthreads();
        if (tid < S2) sc[tid] = expf(sc[tid] - red[0]);
        __syncthreads();
        if (tid == 0) {
            float su = 0.f;
            for (int t = 0; t < S2; t++) su += sc[t];
            red[1] = 1.f / su;
        }
        __syncthreads();

        float acc = 0.f;
        #pragma unroll 8
        for (int t = 0; t < S2; t++)
            acc += sc[t] * fb[t * DA + tid];
        float ta = acc * red[1] - bs[tid];
        float ev = es[tid];

        long go = ((long)b * S1 + s) * (4 * DA) + tid;
        float vals[4] = {fast_tanh(ev), fast_tanh(ta),
                         fast_tanh(ev * ta), fast_tanh(ev - ta)};
        #pragma unroll
        for (int q = 0; q < 4; q++) {
            __nv_bfloat16 h = __float2bfloat16(vals[q]);
            g_gh[go + q * DA] = h;
            g_gl[go + q * DA] = __float2bfloat16(vals[q] - __bfloat162float(h));
        }
    }
}

// ---------------------------------------------------------------------------
extern "C" void kernel_launch(void* const* d_in, const int* in_sizes, int n_in,
                              void* d_out, int out_size) {
    const float* video = (const float*)d_in[0];
    const float* text  = (const float*)d_in[1];
    const float* w1    = (const float*)d_in[2];
    const float* w2    = (const float*)d_in[3];
    const float* w3    = (const float*)d_in[4];
    const float* bias  = (const float*)d_in[5];
    const float* w4    = (const float*)d_in[6];
    const float* b4    = (const float*)d_in[7];
    float* out = (float*)d_out;

    float* pe;
    __nv_bfloat16 *pvh, *pvl, *pgh, *pgl, *p1h, *p1l, *p4h, *p4l;
    cudaGetSymbolAddress((void**)&pe, g_e);
    cudaGetSymbolAddress((void**)&pvh, g_vh);
    cudaGetSymbolAddress((void**)&pvl, g_vl);
    cudaGetSymbolAddress((void**)&pgh, g_gh);
    cudaGetSymbolAddress((void**)&pgl, g_gl);
    cudaGetSymbolAddress((void**)&p1h, g_w1h);
    cudaGetSymbolAddress((void**)&p1l, g_w1l);
    cudaGetSymbolAddress((void**)&p4h, g_w4h);
    cudaGetSymbolAddress((void**)&p4l, g_w4l);

    // weight prep (transpose + split bf16)
    k_prep<<<(DA * DV + 255) / 256, 256>>>(w1, p1h, p1l, DA, DA, DV);
    k_prep<<<(DO_PAD * 4 * DA + 255) / 256, 256>>>(w4, p4h, p4l, DO, DO_PAD, 4 * DA);
    // video split to hi/lo bf16
    int v4 = NB * S1 * DV / 4;
    k_split<<<(v4 + 255) / 256, 256>>>(video, pvh, pvl, v4);
    // f = text @ w2
    k_text_proj<<<dim3(NB, S2), 256>>>(text, w2);
    // e = video @ w1  (8192x256, K=1024) — mma.sync split-bf16
    k_gemm_mma<<<dim3((NB * S1) / 128, DA / 128), 256>>>(
        pvh, pvl, p1h, p1l, nullptr, pe, DA, DV);
    // fused attention -> g (split bf16)
    k_attn<<<dim3(NB, S1 / 32), 256>>>(w3, bias);
    // out = g @ w4 + b4  (8192x500, K=1024) — mma.sync split-bf16
    k_gemm_mma<<<dim3((NB * S1) / 128, DO_PAD / 128), 256>>>(
        pgh, pgl, p4h, p4l, b4, out, DO, 4 * DA);
}

// round 9
// speedup vs baseline: 3.0257x; 1.0950x over previous
#include <cuda_runtime.h>
#include <cuda_bf16.h>
#include <math.h>
#include <cstdint>

#define NB 16
#define S1 512
#define S2 40
#define DV 1024
#define DT 300
#define DA 256
#define DO 500
#define DO_PAD 512

// ---------------------------------------------------------------------------
// Scratch (static device globals: allocation-free)
// ---------------------------------------------------------------------------
__device__ float g_f[NB * S2 * DA];                    // f = text @ w2    (16,40,256)
__device__ float g_e[NB * S1 * DA];                    // e = video @ w1   (16,512,256)
__device__ __nv_bfloat16 g_vh[NB * S1 * DV];           // video split hi
__device__ __nv_bfloat16 g_vl[NB * S1 * DV];           // video split lo
__device__ __nv_bfloat16 g_gh[NB * S1 * 4 * DA];       // tanh(cont) split hi
__device__ __nv_bfloat16 g_gl[NB * S1 * 4 * DA];       // tanh(cont) split lo
__device__ __nv_bfloat16 g_w1h[DA * DV];               // w1^T hi [256,1024]
__device__ __nv_bfloat16 g_w1l[DA * DV];               // w1^T lo
__device__ __nv_bfloat16 g_w4h[DO_PAD * (4 * DA)];     // w4^T hi [512,1024] (rows>=500 zero)
__device__ __nv_bfloat16 g_w4l[DO_PAD * (4 * DA)];     // w4^T lo

// ---------------------------------------------------------------------------
// Fast accurate tanh: 2 MUFU + ~5 ALU, rel err ~1e-6
// ---------------------------------------------------------------------------
__device__ __forceinline__ float fast_tanh(float x) {
    float ax = fabsf(x);
    float e = __expf(-2.f * ax);
    float t = __fdividef(1.f - e, 1.f + e);
    return copysignf(t, x);
}

// mma.sync m16n8k16 bf16 (sm_80+ base feature; NOT arch-specific)
#define MMA16816(c, a0, a1, a2, a3, b0, b1)                                  \
    asm volatile(                                                            \
        "mma.sync.aligned.m16n8k16.row.col.f32.bf16.bf16.f32 "               \
        "{%0,%1,%2,%3}, {%4,%5,%6,%7}, {%8,%9}, {%0,%1,%2,%3};"              \
        : "+f"((c)[0]), "+f"((c)[1]), "+f"((c)[2]), "+f"((c)[3])             \
        : "r"(a0), "r"(a1), "r"(a2), "r"(a3), "r"(b0), "r"(b1))

__device__ __forceinline__ void split2(float v, __nv_bfloat16& h, __nv_bfloat16& l) {
    h = __float2bfloat16(v);
    l = __float2bfloat16(v - __bfloat162float(h));
}

// ---------------------------------------------------------------------------
// k_pre: fused prologue — one launch, four independent jobs by block range.
//   [0, 1024)           : w1^T split prep
//   [1024, 3072)        : w4^T split prep (rows >= 500 zeroed)
//   [3072, 11264)       : video fp32 -> hi/lo bf16 split (float4 per thread)
//   [11264, 11904)      : text_proj, one (b,t) row per block, 4 accumulators
// ---------------------------------------------------------------------------
#define NBLK_W1 ((DA * DV) / 256)               // 1024
#define NBLK_W4 ((DO_PAD * 4 * DA) / 256)       // 2048
#define NBLK_V  ((NB * S1 * DV / 4) / 256)      // 8192
#define NBLK_T  (NB * S2)                       // 640

__global__ __launch_bounds__(256) void k_pre(const float* __restrict__ w1,
                                             const float* __restrict__ w4,
                                             const float* __restrict__ video,
                                             const float* __restrict__ text,
                                             const float* __restrict__ w2) {
    __shared__ float ts[DT];
    int bid = blockIdx.x, tid = threadIdx.x;

    if (bid < NBLK_W1) {
        // w1^T: out[n*DV + k] = split(w1[k*DA + n])
        int idx = bid * 256 + tid;
        int n = idx >> 10, k = idx & (DV - 1);
        float v = w1[(long)k * DA + n];
        split2(v, g_w1h[idx], g_w1l[idx]);
    } else if (bid < NBLK_W1 + NBLK_W4) {
        // w4^T: out[n*(4*DA) + k] = split(w4[k*DO + n]); n >= DO -> 0
        int idx = (bid - NBLK_W1) * 256 + tid;
        int n = idx >> 10, k = idx & (4 * DA - 1);
        float v = (n < DO) ? w4[(long)k * DO + n] : 0.f;
        split2(v, g_w4h[idx], g_w4l[idx]);
    } else if (bid < NBLK_W1 + NBLK_W4 + NBLK_V) {
        // video split, float4 granularity
        int i = (bid - NBLK_W1 - NBLK_W4) * 256 + tid;
        float4 v = ((const float4*)video)[i];
        __nv_bfloat16 hh[4], ll[4];
        split2(v.x, hh[0], ll[0]);
        split2(v.y, hh[1], ll[1]);
        split2(v.z, hh[2], ll[2]);
        split2(v.w, hh[3], ll[3]);
        *(uint2*)&g_vh[4 * i] = *(uint2*)hh;
        *(uint2*)&g_vl[4 * i] = *(uint2*)ll;
    } else {
        // text_proj: one (b,t) row, tid = a. 4 accumulators break FFMA chain.
        int row = bid - (NBLK_W1 + NBLK_W4 + NBLK_V);
        for (int i = tid; i < DT; i += 256)
            ts[i] = text[row * DT + i];
        __syncthreads();

        float a0 = 0.f, a1 = 0.f, a2 = 0.f, a3 = 0.f;
        const float* w2p = w2 + tid;
        #pragma unroll 5
        for (int d = 0; d < DT; d += 4) {
            a0 += ts[d]     * w2p[(d)     * DA];
            a1 += ts[d + 1] * w2p[(d + 1) * DA];
            a2 += ts[d + 2] * w2p[(d + 2) * DA];
            a3 += ts[d + 3] * w2p[(d + 3) * DA];
        }
        g_f[row * DA + tid] = (a0 + a1) + (a2 + a3);
    }
}

// ---------------------------------------------------------------------------
// Tensor-core GEMM via mma.sync: C[M,N] = A @ Bt^T (+bias), split-bf16.
// CTA 128x128, BK=32, 8 warps in 2(M)x4(N), 4x4 m16n8k16 tiles per warp.
// Register-prefetch pipeline: next chunk's LDGs issued before MMA phase.
// ---------------------------------------------------------------------------
#define PITCH 40   // bf16 units per smem row (32 + 8 pad)

__global__ __launch_bounds__(256) void k_gemm_mma(
    const __nv_bfloat16* __restrict__ Ah, const __nv_bfloat16* __restrict__ Al,
    const __nv_bfloat16* __restrict__ Bh, const __nv_bfloat16* __restrict__ Bl,
    const float* __restrict__ bias, float* __restrict__ C, int N, int K) {
    __shared__ __nv_bfloat16 sAh[128 * PITCH];
    __shared__ __nv_bfloat16 sAl[128 * PITCH];
    __shared__ __nv_bfloat16 sBh[128 * PITCH];
    __shared__ __nv_bfloat16 sBl[128 * PITCH];

    int tid = threadIdx.x, lane = tid & 31, wid = tid >> 5;
    int g = lane >> 2, tg = lane & 3;
    int brow = blockIdx.x * 128, bn = blockIdx.y * 128;
    int wm = (wid >> 2) * 64, wn = (wid & 3) * 32;

    float acc[4][4][4];
    #pragma unroll
    for (int mi = 0; mi < 4; mi++)
        #pragma unroll
        for (int ni = 0; ni < 4; ni++)
            #pragma unroll
            for (int q = 0; q < 4; q++) acc[mi][ni][q] = 0.f;

    int lrow = tid >> 2;
    int lseg = tid & 3;

    uint4 ra_h[2], ra_l[2], rb_h[2], rb_l[2];

    #pragma unroll
    for (int it = 0; it < 2; it++) {
        int r = it * 64 + lrow;
        int c = lseg * 8;
        long ga = (long)(brow + r) * K + c;
        long gb = (long)(bn + r) * K + c;
        ra_h[it] = *(const uint4*)&Ah[ga];
        ra_l[it] = *(const uint4*)&Al[ga];
        rb_h[it] = *(const uint4*)&Bh[gb];
        rb_l[it] = *(const uint4*)&Bl[gb];
    }

    for (int kc = 0; kc < K; kc += 32) {
        #pragma unroll
        for (int it = 0; it < 2; it++) {
            int so = (it * 64 + lrow) * PITCH + lseg * 8;
            *(uint4*)&sAh[so] = ra_h[it];
            *(uint4*)&sAl[so] = ra_l[it];
            *(uint4*)&sBh[so] = rb_h[it];
            *(uint4*)&sBl[so] = rb_l[it];
        }
        __syncthreads();

        if (kc + 32 < K) {
            #pragma unroll
            for (int it = 0; it < 2; it++) {
                int r = it * 64 + lrow;
                int c = kc + 32 + lseg * 8;
                long ga = (long)(brow + r) * K + c;
                long gb = (long)(bn + r) * K + c;
                ra_h[it] = *(const uint4*)&Ah[ga];
                ra_l[it] = *(const uint4*)&Al[ga];
                rb_h[it] = *(const uint4*)&Bh[gb];
                rb_l[it] = *(const uint4*)&Bl[gb];
            }
        }

        #pragma unroll
        for (int ks = 0; ks < 2; ks++) {
            int kb = ks * 16 + 2 * tg;
            uint32_t bh0[4], bh1[4], bl0[4], bl1[4];
            #pragma unroll
            for (int ni = 0; ni < 4; ni++) {
                int br = (wn + ni * 8 + g) * PITCH;
                bh0[ni] = *(const uint32_t*)&sBh[br + kb];
                bh1[ni] = *(const uint32_t*)&sBh[br + kb + 8];
                bl0[ni] = *(const uint32_t*)&sBl[br + kb];
                bl1[ni] = *(const uint32_t*)&sBl[br + kb + 8];
            }
            #pragma unroll
            for (int mi = 0; mi < 4; mi++) {
                int ar0 = (wm + mi * 16 + g) * PITCH;
                int ar1 = ar0 + 8 * PITCH;
                uint32_t ah0 = *(const uint32_t*)&sAh[ar0 + kb];
                uint32_t ah1 = *(const uint32_t*)&sAh[ar1 + kb];
                uint32_t ah2 = *(const uint32_t*)&sAh[ar0 + kb + 8];
                uint32_t ah3 = *(const uint32_t*)&sAh[ar1 + kb + 8];
                uint32_t al0 = *(const uint32_t*)&sAl[ar0 + kb];
                uint32_t al1 = *(const uint32_t*)&sAl[ar1 + kb];
                uint32_t al2 = *(const uint32_t*)&sAl[ar0 + kb + 8];
                uint32_t al3 = *(const uint32_t*)&sAl[ar1 + kb + 8];
                #pragma unroll
                for (int ni = 0; ni < 4; ni++) {
                    MMA16816(acc[mi][ni], ah0, ah1, ah2, ah3, bh0[ni], bh1[ni]);
                    MMA16816(acc[mi][ni], ah0, ah1, ah2, ah3, bl0[ni], bl1[ni]);
                    MMA16816(acc[mi][ni], al0, al1, al2, al3, bh0[ni], bh1[ni]);
                }
            }
        }
        __syncthreads();
    }

    #pragma unroll
    for (int mi = 0; mi < 4; mi++) {
        int row = brow + wm + mi * 16 + g;
        #pragma unroll
        for (int ni = 0; ni < 4; ni++) {
            int col = bn + wn + ni * 8 + 2 * tg;
            if (col < N) {
                float b0 = bias ? bias[col] : 0.f;
                float b1 = bias ? bias[col + 1] : 0.f;
                *(float2*)&C[(long)row * N + col] =
                    make_float2(acc[mi][ni][0] + b0, acc[mi][ni][1] + b1);
                *(float2*)&C[(long)(row + 8) * N + col] =
                    make_float2(acc[mi][ni][2] + b0, acc[mi][ni][3] + b1);
            }
        }
    }
}

// ---------------------------------------------------------------------------
// k_attn: fused attention; 4 syncthreads per row (softmax stats in warp 0).
// ---------------------------------------------------------------------------
__global__ __launch_bounds__(256) void k_attn(const float* __restrict__ w3,
                                              const float* __restrict__ bias) {
    __shared__ float fb[S2 * DA];
    __shared__ float es[DA];
    __shared__ float w3s[DA];
    __shared__ float bs[DA];
    __shared__ float sc[S2];
    __shared__ float inv_s;

    int tid = threadIdx.x;
    int b = blockIdx.x, s0 = blockIdx.y * 32;
    int warp = tid >> 5, lane = tid & 31;

    w3s[tid] = w3[tid];
    bs[tid] = bias[tid];
    __syncthreads();
    for (int i = tid; i < S2 * DA; i += 256)
        fb[i] = g_f[b * S2 * DA + i] + bs[i & (DA - 1)];

    for (int r = 0; r < 32; r++) {
        int s = s0 + r;
        __syncthreads();                           // S_a: guards prev stage3 + fb fill
        es[tid] = g_e[((long)b * S1 + s) * DA + tid];
        __syncthreads();                           // S_b

        // stage 1: logits
        #pragma unroll
        for (int tt = 0; tt < 5; tt++) {
            int t = warp + 8 * tt;
            float p = 0.f;
            #pragma unroll
            for (int j = 0; j < 8; j++) {
                int a = lane + 32 * j;
                p += fast_tanh(es[a] + fb[t * DA + a]) * w3s[a];
            }
            #pragma unroll
            for (int off = 16; off; off >>= 1)
                p += __shfl_xor_sync(0xffffffffu, p, off);
            if (lane == 0) sc[t] = p;
        }
        __syncthreads();                           // S_c

        // stage 2: softmax stats entirely in warp 0
        if (warp == 0) {
            float v0 = sc[lane];
            float v1 = (lane + 32 < S2) ? sc[lane + 32] : -3.4e38f;
            float m = fmaxf(v0, v1);
            #pragma unroll
            for (int off = 16; off; off >>= 1)
                m = fmaxf(m, __shfl_xor_sync(0xffffffffu, m, off));
            float e0 = __expf(v0 - m);
            float e1 = (lane + 32 < S2) ? __expf(v1 - m) : 0.f;
            float su = e0 + e1;
            #pragma unroll
            for (int off = 16; off; off >>= 1)
                su += __shfl_xor_sync(0xffffffffu, su, off);
            sc[lane] = e0;
            if (lane + 32 < S2) sc[lane + 32] = e1;
            if (lane == 0) inv_s = 1.f / su;
        }
        __syncthreads();                           // S_d

        // stage 3+4: text_attn + features -> split bf16
        float acc = 0.f;
        #pragma unroll 8
        for (int t = 0; t < S2; t++)
            acc += sc[t] * fb[t * DA + tid];
        float ta = acc * inv_s - bs[tid];
        float ev = es[tid];

        long go = ((long)b * S1 + s) * (4 * DA) + tid;
        float vals[4] = {fast_tanh(ev), fast_tanh(ta),
                         fast_tanh(ev * ta), fast_tanh(ev - ta)};
        #pragma unroll
        for (int q = 0; q < 4; q++) {
            __nv_bfloat16 h = __float2bfloat16(vals[q]);
            g_gh[go + q * DA] = h;
            g_gl[go + q * DA] = __float2bfloat16(vals[q] - __bfloat162float(h));
        }
    }
}

// ---------------------------------------------------------------------------
extern "C" void kernel_launch(void* const* d_in, const int* in_sizes, int n_in,
                              void* d_out, int out_size) {
    const float* video = (const float*)d_in[0];
    const float* text  = (const float*)d_in[1];
    const float* w1    = (const float*)d_in[2];
    const float* w2    = (const float*)d_in[3];
    const float* w3    = (const float*)d_in[4];
    const float* bias  = (const float*)d_in[5];
    const float* w4    = (const float*)d_in[6];
    const float* b4    = (const float*)d_in[7];
    float* out = (float*)d_out;

    float* pe;
    __nv_bfloat16 *pvh, *pvl, *pgh, *pgl, *p1h, *p1l, *p4h, *p4l;
    cudaGetSymbolAddress((void**)&pe, g_e);
    cudaGetSymbolAddress((void**)&pvh, g_vh);
    cudaGetSymbolAddress((void**)&pvl, g_vl);
    cudaGetSymbolAddress((void**)&pgh, g_gh);
    cudaGetSymbolAddress((void**)&pgl, g_gl);
    cudaGetSymbolAddress((void**)&p1h, g_w1h);
    cudaGetSymbolAddress((void**)&p1l, g_w1l);
    cudaGetSymbolAddress((void**)&p4h, g_w4h);
    cudaGetSymbolAddress((void**)&p4l, g_w4l);

    // fused prologue: w1/w4 prep + video split + text_proj in one launch
    k_pre<<<NBLK_W1 + NBLK_W4 + NBLK_V + NBLK_T, 256>>>(w1, w4, video, text, w2);
    // e = video @ w1  (8192x256, K=1024) — mma.sync split-bf16
    k_gemm_mma<<<dim3((NB * S1) / 128, DA / 128), 256>>>(
        pvh, pvl, p1h, p1l, nullptr, pe, DA, DV);
    // fused attention -> g (split bf16)
    k_attn<<<dim3(NB, S1 / 32), 256>>>(w3, bias);
    // out = g @ w4 + b4  (8192x500, K=1024) — mma.sync split-bf16
    k_gemm_mma<<<dim3((NB * S1) / 128, DO_PAD / 128), 256>>>(
        pgh, pgl, p4h, p4l, b4, out, DO, 4 * DA);
}

// round 10
// speedup vs baseline: 3.1487x; 1.0406x over previous
#include <cuda_runtime.h>
#include <cuda_bf16.h>
#include <math.h>
#include <cstdint>

#define NB 16
#define S1 512
#define S2 40
#define DV 1024
#define DT 300
#define DA 256
#define DO 500
#define DO_PAD 512

// ---------------------------------------------------------------------------
// Scratch (static device globals: allocation-free)
// ---------------------------------------------------------------------------
__device__ float g_f[NB * S2 * DA];                    // f = text @ w2    (16,40,256)
__device__ float g_e[NB * S1 * DA];                    // e = video @ w1   (16,512,256)
__device__ __nv_bfloat16 g_vh[NB * S1 * DV];           // video split hi
__device__ __nv_bfloat16 g_vl[NB * S1 * DV];           // video split lo
__device__ __nv_bfloat16 g_gh[NB * S1 * 4 * DA];       // tanh(cont) split hi
__device__ __nv_bfloat16 g_gl[NB * S1 * 4 * DA];       // tanh(cont) split lo
__device__ __nv_bfloat16 g_w1h[DA * DV];               // w1^T hi [256,1024]
__device__ __nv_bfloat16 g_w1l[DA * DV];               // w1^T lo
__device__ __nv_bfloat16 g_w4h[DO_PAD * (4 * DA)];     // w4^T hi [512,1024] (rows>=500 zero)
__device__ __nv_bfloat16 g_w4l[DO_PAD * (4 * DA)];     // w4^T lo

// ---------------------------------------------------------------------------
// Fast accurate tanh: 2 MUFU + ~5 ALU, rel err ~1e-6
// ---------------------------------------------------------------------------
__device__ __forceinline__ float fast_tanh(float x) {
    float ax = fabsf(x);
    float e = __expf(-2.f * ax);
    float t = __fdividef(1.f - e, 1.f + e);
    return copysignf(t, x);
}

// mma.sync m16n8k16 bf16 (sm_80+ base feature; NOT arch-specific)
#define MMA16816(c, a0, a1, a2, a3, b0, b1)                                  \
    asm volatile(                                                            \
        "mma.sync.aligned.m16n8k16.row.col.f32.bf16.bf16.f32 "               \
        "{%0,%1,%2,%3}, {%4,%5,%6,%7}, {%8,%9}, {%0,%1,%2,%3};"              \
        : "+f"((c)[0]), "+f"((c)[1]), "+f"((c)[2]), "+f"((c)[3])             \
        : "r"(a0), "r"(a1), "r"(a2), "r"(a3), "r"(b0), "r"(b1))

__device__ __forceinline__ void split2(float v, __nv_bfloat16& h, __nv_bfloat16& l) {
    h = __float2bfloat16(v);
    l = __float2bfloat16(v - __bfloat162float(h));
}

// ---------------------------------------------------------------------------
// k_pre: fused prologue — one launch, four independent jobs by block range.
// ---------------------------------------------------------------------------
#define NBLK_W1 ((DA * DV) / 256)               // 1024
#define NBLK_W4 ((DO_PAD * 4 * DA) / 256)       // 2048
#define NBLK_V  ((NB * S1 * DV / 4) / 256)      // 8192
#define NBLK_T  (NB * S2)                       // 640

__global__ __launch_bounds__(256) void k_pre(const float* __restrict__ w1,
                                             const float* __restrict__ w4,
                                             const float* __restrict__ video,
                                             const float* __restrict__ text,
                                             const float* __restrict__ w2) {
    __shared__ float ts[DT];
    int bid = blockIdx.x, tid = threadIdx.x;

    if (bid < NBLK_W1) {
        int idx = bid * 256 + tid;
        int n = idx >> 10, k = idx & (DV - 1);
        float v = w1[(long)k * DA + n];
        split2(v, g_w1h[idx], g_w1l[idx]);
    } else if (bid < NBLK_W1 + NBLK_W4) {
        int idx = (bid - NBLK_W1) * 256 + tid;
        int n = idx >> 10, k = idx & (4 * DA - 1);
        float v = (n < DO) ? w4[(long)k * DO + n] : 0.f;
        split2(v, g_w4h[idx], g_w4l[idx]);
    } else if (bid < NBLK_W1 + NBLK_W4 + NBLK_V) {
        int i = (bid - NBLK_W1 - NBLK_W4) * 256 + tid;
        float4 v = ((const float4*)video)[i];
        __nv_bfloat16 hh[4], ll[4];
        split2(v.x, hh[0], ll[0]);
        split2(v.y, hh[1], ll[1]);
        split2(v.z, hh[2], ll[2]);
        split2(v.w, hh[3], ll[3]);
        *(uint2*)&g_vh[4 * i] = *(uint2*)hh;
        *(uint2*)&g_vl[4 * i] = *(uint2*)ll;
    } else {
        int row = bid - (NBLK_W1 + NBLK_W4 + NBLK_V);
        for (int i = tid; i < DT; i += 256)
            ts[i] = text[row * DT + i];
        __syncthreads();

        float a0 = 0.f, a1 = 0.f, a2 = 0.f, a3 = 0.f;
        const float* w2p = w2 + tid;
        #pragma unroll 5
        for (int d = 0; d < DT; d += 4) {
            a0 += ts[d]     * w2p[(d)     * DA];
            a1 += ts[d + 1] * w2p[(d + 1) * DA];
            a2 += ts[d + 2] * w2p[(d + 2) * DA];
            a3 += ts[d + 3] * w2p[(d + 3) * DA];
        }
        g_f[row * DA + tid] = (a0 + a1) + (a2 + a3);
    }
}

// ---------------------------------------------------------------------------
// Tensor-core GEMM via mma.sync: C[M,N] = A @ Bt^T (+bias), split-bf16.
// CTA 128x128, BK=32, 8 warps in 2(M)x4(N), 4x4 m16n8k16 tiles per warp.
// DOUBLE-BUFFERED dynamic smem: one __syncthreads per K-chunk; MMA on stage
// `cur` overlaps LDG of next chunk; STS targets stage cur^1.
// ---------------------------------------------------------------------------
#define PITCH 40                 // bf16 units per smem row (32 + 8 pad)
#define SSZ   (128 * PITCH)      // bf16 per array per stage
#define GSMEM (2 * 4 * SSZ * (int)sizeof(__nv_bfloat16))   // 81920 B

__global__ __launch_bounds__(256) void k_gemm_mma(
    const __nv_bfloat16* __restrict__ Ah, const __nv_bfloat16* __restrict__ Al,
    const __nv_bfloat16* __restrict__ Bh, const __nv_bfloat16* __restrict__ Bl,
    const float* __restrict__ bias, float* __restrict__ C, int N, int K) {
    extern __shared__ __nv_bfloat16 sm[];

    int tid = threadIdx.x, lane = tid & 31, wid = tid >> 5;
    int g = lane >> 2, tg = lane & 3;
    int brow = blockIdx.x * 128, bn = blockIdx.y * 128;
    int wm = (wid >> 2) * 64, wn = (wid & 3) * 32;

    float acc[4][4][4];
    #pragma unroll
    for (int mi = 0; mi < 4; mi++)
        #pragma unroll
        for (int ni = 0; ni < 4; ni++)
            #pragma unroll
            for (int q = 0; q < 4; q++) acc[mi][ni][q] = 0.f;

    int lrow = tid >> 2;
    int lseg = tid & 3;

    uint4 ra_h[2], ra_l[2], rb_h[2], rb_l[2];

    // LDG chunk 0
    #pragma unroll
    for (int it = 0; it < 2; it++) {
        int r = it * 64 + lrow;
        int c = lseg * 8;
        long ga = (long)(brow + r) * K + c;
        long gb = (long)(bn + r) * K + c;
        ra_h[it] = *(const uint4*)&Ah[ga];
        ra_l[it] = *(const uint4*)&Al[ga];
        rb_h[it] = *(const uint4*)&Bh[gb];
        rb_l[it] = *(const uint4*)&Bl[gb];
    }
    // STS chunk 0 -> stage 0
    #pragma unroll
    for (int it = 0; it < 2; it++) {
        int so = (it * 64 + lrow) * PITCH + lseg * 8;
        *(uint4*)&sm[0 * SSZ + so] = ra_h[it];
        *(uint4*)&sm[1 * SSZ + so] = ra_l[it];
        *(uint4*)&sm[2 * SSZ + so] = rb_h[it];
        *(uint4*)&sm[3 * SSZ + so] = rb_l[it];
    }
    __syncthreads();

    int cur = 0;
    for (int kc = 0; kc < K; kc += 32) {
        bool has_next = (kc + 32 < K);
        if (has_next) {
            #pragma unroll
            for (int it = 0; it < 2; it++) {
                int r = it * 64 + lrow;
                int c = kc + 32 + lseg * 8;
                long ga = (long)(brow + r) * K + c;
                long gb = (long)(bn + r) * K + c;
                ra_h[it] = *(const uint4*)&Ah[ga];
                ra_l[it] = *(const uint4*)&Al[ga];
                rb_h[it] = *(const uint4*)&Bh[gb];
                rb_l[it] = *(const uint4*)&Bl[gb];
            }
        }

        const __nv_bfloat16* sAh = sm + (cur * 4 + 0) * SSZ;
        const __nv_bfloat16* sAl = sm + (cur * 4 + 1) * SSZ;
        const __nv_bfloat16* sBh = sm + (cur * 4 + 2) * SSZ;
        const __nv_bfloat16* sBl = sm + (cur * 4 + 3) * SSZ;

        #pragma unroll
        for (int ks = 0; ks < 2; ks++) {
            int kb = ks * 16 + 2 * tg;
            uint32_t bh0[4], bh1[4], bl0[4], bl1[4];
            #pragma unroll
            for (int ni = 0; ni < 4; ni++) {
                int br = (wn + ni * 8 + g) * PITCH;
                bh0[ni] = *(const uint32_t*)&sBh[br + kb];
                bh1[ni] = *(const uint32_t*)&sBh[br + kb + 8];
                bl0[ni] = *(const uint32_t*)&sBl[br + kb];
                bl1[ni] = *(const uint32_t*)&sBl[br + kb + 8];
            }
            #pragma unroll
            for (int mi = 0; mi < 4; mi++) {
                int ar0 = (wm + mi * 16 + g) * PITCH;
                int ar1 = ar0 + 8 * PITCH;
                uint32_t ah0 = *(const uint32_t*)&sAh[ar0 + kb];
                uint32_t ah1 = *(const uint32_t*)&sAh[ar1 + kb];
                uint32_t ah2 = *(const uint32_t*)&sAh[ar0 + kb + 8];
                uint32_t ah3 = *(const uint32_t*)&sAh[ar1 + kb + 8];
                uint32_t al0 = *(const uint32_t*)&sAl[ar0 + kb];
                uint32_t al1 = *(const uint32_t*)&sAl[ar1 + kb];
                uint32_t al2 = *(const uint32_t*)&sAl[ar0 + kb + 8];
                uint32_t al3 = *(const uint32_t*)&sAl[ar1 + kb + 8];
                #pragma unroll
                for (int ni = 0; ni < 4; ni++) {
                    MMA16816(acc[mi][ni], ah0, ah1, ah2, ah3, bh0[ni], bh1[ni]);
                    MMA16816(acc[mi][ni], ah0, ah1, ah2, ah3, bl0[ni], bl1[ni]);
                    MMA16816(acc[mi][ni], al0, al1, al2, al3, bh0[ni], bh1[ni]);
                }
            }
        }

        if (has_next) {
            int nxt = cur ^ 1;
            #pragma unroll
            for (int it = 0; it < 2; it++) {
                int so = (it * 64 + lrow) * PITCH + lseg * 8;
                *(uint4*)&sm[(nxt * 4 + 0) * SSZ + so] = ra_h[it];
                *(uint4*)&sm[(nxt * 4 + 1) * SSZ + so] = ra_l[it];
                *(uint4*)&sm[(nxt * 4 + 2) * SSZ + so] = rb_h[it];
                *(uint4*)&sm[(nxt * 4 + 3) * SSZ + so] = rb_l[it];
            }
            __syncthreads();
            cur = nxt;
        }
    }

    #pragma unroll
    for (int mi = 0; mi < 4; mi++) {
        int row = brow + wm + mi * 16 + g;
        #pragma unroll
        for (int ni = 0; ni < 4; ni++) {
            int col = bn + wn + ni * 8 + 2 * tg;
            if (col < N) {
                float b0 = bias ? bias[col] : 0.f;
                float b1 = bias ? bias[col + 1] : 0.f;
                *(float2*)&C[(long)row * N + col] =
                    make_float2(acc[mi][ni][0] + b0, acc[mi][ni][1] + b1);
                *(float2*)&C[(long)(row + 8) * N + col] =
                    make_float2(acc[mi][ni][2] + b0, acc[mi][ni][3] + b1);
            }
        }
    }
}

// ---------------------------------------------------------------------------
// k_attn: fused attention; 16 rows per block (grid x2 for barrier overlap).
// ---------------------------------------------------------------------------
#define ROWS_PER_BLK 16

__global__ __launch_bounds__(256) void k_attn(const float* __restrict__ w3,
                                              const float* __restrict__ bias) {
    __shared__ float fb[S2 * DA];
    __shared__ float es[DA];
    __shared__ float w3s[DA];
    __shared__ float bs[DA];
    __shared__ float sc[S2];
    __shared__ float inv_s;

    int tid = threadIdx.x;
    int b = blockIdx.x, s0 = blockIdx.y * ROWS_PER_BLK;
    int warp = tid >> 5, lane = tid & 31;

    w3s[tid] = w3[tid];
    bs[tid] = bias[tid];
    __syncthreads();
    for (int i = tid; i < S2 * DA; i += 256)
        fb[i] = g_f[b * S2 * DA + i] + bs[i & (DA - 1)];

    for (int r = 0; r < ROWS_PER_BLK; r++) {
        int s = s0 + r;
        __syncthreads();
        es[tid] = g_e[((long)b * S1 + s) * DA + tid];
        __syncthreads();

        // stage 1: logits
        #pragma unroll
        for (int tt = 0; tt < 5; tt++) {
            int t = warp + 8 * tt;
            float p = 0.f;
            #pragma unroll
            for (int j = 0; j < 8; j++) {
                int a = lane + 32 * j;
                p += fast_tanh(es[a] + fb[t * DA + a]) * w3s[a];
            }
            #pragma unroll
            for (int off = 16; off; off >>= 1)
                p += __shfl_xor_sync(0xffffffffu, p, off);
            if (lane == 0) sc[t] = p;
        }
        __syncthreads();

        // stage 2: softmax stats entirely in warp 0
        if (warp == 0) {
            float v0 = sc[lane];
            float v1 = (lane + 32 < S2) ? sc[lane + 32] : -3.4e38f;
            float m = fmaxf(v0, v1);
            #pragma unroll
            for (int off = 16; off; off >>= 1)
                m = fmaxf(m, __shfl_xor_sync(0xffffffffu, m, off));
            float e0 = __expf(v0 - m);
            float e1 = (lane + 32 < S2) ? __expf(v1 - m) : 0.f;
            float su = e0 + e1;
            #pragma unroll
            for (int off = 16; off; off >>= 1)
                su += __shfl_xor_sync(0xffffffffu, su, off);
            sc[lane] = e0;
            if (lane + 32 < S2) sc[lane + 32] = e1;
            if (lane == 0) inv_s = 1.f / su;
        }
        __syncthreads();

        // stage 3+4: text_attn + features -> split bf16
        float acc = 0.f;
        #pragma unroll 8
        for (int t = 0; t < S2; t++)
            acc += sc[t] * fb[t * DA + tid];
        float ta = acc * inv_s - bs[tid];
        float ev = es[tid];

        long go = ((long)b * S1 + s) * (4 * DA) + tid;
        float vals[4] = {fast_tanh(ev), fast_tanh(ta),
                         fast_tanh(ev * ta), fast_tanh(ev - ta)};
        #pragma unroll
        for (int q = 0; q < 4; q++) {
            __nv_bfloat16 h = __float2bfloat16(vals[q]);
            g_gh[go + q * DA] = h;
            g_gl[go + q * DA] = __float2bfloat16(vals[q] - __bfloat162float(h));
        }
    }
}

// ---------------------------------------------------------------------------
extern "C" void kernel_launch(void* const* d_in, const int* in_sizes, int n_in,
                              void* d_out, int out_size) {
    const float* video = (const float*)d_in[0];
    const float* text  = (const float*)d_in[1];
    const float* w1    = (const float*)d_in[2];
    const float* w2    = (const float*)d_in[3];
    const float* w3    = (const float*)d_in[4];
    const float* bias  = (const float*)d_in[5];
    const float* w4    = (const float*)d_in[6];
    const float* b4    = (const float*)d_in[7];
    float* out = (float*)d_out;

    float* pe;
    __nv_bfloat16 *pvh, *pvl, *pgh, *pgl, *p1h, *p1l, *p4h, *p4l;
    cudaGetSymbolAddress((void**)&pe, g_e);
    cudaGetSymbolAddress((void**)&pvh, g_vh);
    cudaGetSymbolAddress((void**)&pvl, g_vl);
    cudaGetSymbolAddress((void**)&pgh, g_gh);
    cudaGetSymbolAddress((void**)&pgl, g_gl);
    cudaGetSymbolAddress((void**)&p1h, g_w1h);
    cudaGetSymbolAddress((void**)&p1l, g_w1l);
    cudaGetSymbolAddress((void**)&p4h, g_w4h);
    cudaGetSymbolAddress((void**)&p4l, g_w4l);

    // dynamic-smem opt-in (no static guard; idempotent, capture-legal)
    cudaFuncSetAttribute(k_gemm_mma, cudaFuncAttributeMaxDynamicSharedMemorySize,
                         GSMEM);

    // fused prologue
    k_pre<<<NBLK_W1 + NBLK_W4 + NBLK_V + NBLK_T, 256>>>(w1, w4, video, text, w2);
    // e = video @ w1  (8192x256, K=1024) — mma.sync split-bf16, double-buffered
    k_gemm_mma<<<dim3((NB * S1) / 128, DA / 128), 256, GSMEM>>>(
        pvh, pvl, p1h, p1l, nullptr, pe, DA, DV);
    // fused attention -> g (split bf16)
    k_attn<<<dim3(NB, S1 / ROWS_PER_BLK), 256>>>(w3, bias);
    // out = g @ w4 + b4  (8192x500, K=1024) — mma.sync split-bf16, double-buffered
    k_gemm_mma<<<dim3((NB * S1) / 128, DO_PAD / 128), 256, GSMEM>>>(
        pgh, pgl, p4h, p4l, b4, out, DO, 4 * DA);
}

// round 11
// speedup vs baseline: 3.1795x; 1.0098x over previous
#include <cuda_runtime.h>
#include <cuda_bf16.h>
#include <math.h>
#include <cstdint>

#define NB 16
#define S1 512
#define S2 40
#define DV 1024
#define DT 300
#define DA 256
#define DO 500
#define DO_PAD 512

// ---------------------------------------------------------------------------
// Scratch (static device globals: allocation-free)
// ---------------------------------------------------------------------------
__device__ float g_f[NB * S2 * DA];                    // f = text @ w2    (16,40,256)
__device__ float g_e[NB * S1 * DA];                    // e = video @ w1   (16,512,256)
__device__ __nv_bfloat16 g_vh[NB * S1 * DV];           // video split hi
__device__ __nv_bfloat16 g_vl[NB * S1 * DV];           // video split lo
__device__ __nv_bfloat16 g_gh[NB * S1 * 4 * DA];       // tanh(cont) split hi
__device__ __nv_bfloat16 g_gl[NB * S1 * 4 * DA];       // tanh(cont) split lo
__device__ __nv_bfloat16 g_w1h[DA * DV];               // w1^T hi [256,1024]
__device__ __nv_bfloat16 g_w1l[DA * DV];               // w1^T lo
__device__ __nv_bfloat16 g_w4h[DO_PAD * (4 * DA)];     // w4^T hi [512,1024] (rows>=500 zero)
__device__ __nv_bfloat16 g_w4l[DO_PAD * (4 * DA)];     // w4^T lo

// ---------------------------------------------------------------------------
// Fast accurate tanh: 2 MUFU + ~5 ALU, rel err ~1e-6
// ---------------------------------------------------------------------------
__device__ __forceinline__ float fast_tanh(float x) {
    float ax = fabsf(x);
    float e = __expf(-2.f * ax);
    float t = __fdividef(1.f - e, 1.f + e);
    return copysignf(t, x);
}

// mma.sync m16n8k16 bf16 (sm_80+ base feature; NOT arch-specific)
#define MMA16816(c, a0, a1, a2, a3, b0, b1)                                  \
    asm volatile(                                                            \
        "mma.sync.aligned.m16n8k16.row.col.f32.bf16.bf16.f32 "               \
        "{%0,%1,%2,%3}, {%4,%5,%6,%7}, {%8,%9}, {%0,%1,%2,%3};"              \
        : "+f"((c)[0]), "+f"((c)[1]), "+f"((c)[2]), "+f"((c)[3])             \
        : "r"(a0), "r"(a1), "r"(a2), "r"(a3), "r"(b0), "r"(b1))

__device__ __forceinline__ void split2(float v, __nv_bfloat16& h, __nv_bfloat16& l) {
    h = __float2bfloat16(v);
    l = __float2bfloat16(v - __bfloat162float(h));
}

// ---------------------------------------------------------------------------
// k_pre: fused prologue — one launch, four independent jobs by block range.
// ---------------------------------------------------------------------------
#define NBLK_W1 ((DA * DV) / 256)               // 1024
#define NBLK_W4 ((DO_PAD * 4 * DA) / 256)       // 2048
#define NBLK_V  ((NB * S1 * DV / 4) / 256)      // 8192
#define NBLK_T  (NB * S2)                       // 640

__global__ __launch_bounds__(256) void k_pre(const float* __restrict__ w1,
                                             const float* __restrict__ w4,
                                             const float* __restrict__ video,
                                             const float* __restrict__ text,
                                             const float* __restrict__ w2) {
    __shared__ float ts[DT];
    int bid = blockIdx.x, tid = threadIdx.x;

    if (bid < NBLK_W1) {
        int idx = bid * 256 + tid;
        int n = idx >> 10, k = idx & (DV - 1);
        float v = w1[(long)k * DA + n];
        split2(v, g_w1h[idx], g_w1l[idx]);
    } else if (bid < NBLK_W1 + NBLK_W4) {
        int idx = (bid - NBLK_W1) * 256 + tid;
        int n = idx >> 10, k = idx & (4 * DA - 1);
        float v = (n < DO) ? w4[(long)k * DO + n] : 0.f;
        split2(v, g_w4h[idx], g_w4l[idx]);
    } else if (bid < NBLK_W1 + NBLK_W4 + NBLK_V) {
        int i = (bid - NBLK_W1 - NBLK_W4) * 256 + tid;
        float4 v = ((const float4*)video)[i];
        __nv_bfloat16 hh[4], ll[4];
        split2(v.x, hh[0], ll[0]);
        split2(v.y, hh[1], ll[1]);
        split2(v.z, hh[2], ll[2]);
        split2(v.w, hh[3], ll[3]);
        *(uint2*)&g_vh[4 * i] = *(uint2*)hh;
        *(uint2*)&g_vl[4 * i] = *(uint2*)ll;
    } else {
        int row = bid - (NBLK_W1 + NBLK_W4 + NBLK_V);
        for (int i = tid; i < DT; i += 256)
            ts[i] = text[row * DT + i];
        __syncthreads();

        float a0 = 0.f, a1 = 0.f, a2 = 0.f, a3 = 0.f;
        const float* w2p = w2 + tid;
        #pragma unroll 5
        for (int d = 0; d < DT; d += 4) {
            a0 += ts[d]     * w2p[(d)     * DA];
            a1 += ts[d + 1] * w2p[(d + 1) * DA];
            a2 += ts[d + 2] * w2p[(d + 2) * DA];
            a3 += ts[d + 3] * w2p[(d + 3) * DA];
        }
        g_f[row * DA + tid] = (a0 + a1) + (a2 + a3);
    }
}

// ---------------------------------------------------------------------------
// Tensor-core GEMM via mma.sync: C[M,N] = A @ Bt^T (+bias), split-bf16.
// CTA 128x128, BK=32, 512 threads / 16 warps in 4(M)x4(N); each warp 32x32
// via 2x4 m16n8k16 tiles. Double-buffered smem, one sync per chunk.
// MMA order: per mi, each split-product sweeps all ni (independent accs)
// before the next product touches the same acc -> RAW spacing of 4.
// ---------------------------------------------------------------------------
#define PITCH 40                 // bf16 units per smem row (32 + 8 pad)
#define SSZ   (128 * PITCH)      // bf16 per array per stage
#define GSMEM (2 * 4 * SSZ * (int)sizeof(__nv_bfloat16))   // 81920 B

__global__ __launch_bounds__(512) void k_gemm_mma(
    const __nv_bfloat16* __restrict__ Ah, const __nv_bfloat16* __restrict__ Al,
    const __nv_bfloat16* __restrict__ Bh, const __nv_bfloat16* __restrict__ Bl,
    const float* __restrict__ bias, float* __restrict__ C, int N, int K) {
    extern __shared__ __nv_bfloat16 sm[];

    int tid = threadIdx.x, lane = tid & 31, wid = tid >> 5;
    int g = lane >> 2, tg = lane & 3;
    int brow = blockIdx.x * 128, bn = blockIdx.y * 128;
    int wm = (wid >> 2) * 32, wn = (wid & 3) * 32;

    float acc[2][4][4];
    #pragma unroll
    for (int mi = 0; mi < 2; mi++)
        #pragma unroll
        for (int ni = 0; ni < 4; ni++)
            #pragma unroll
            for (int q = 0; q < 4; q++) acc[mi][ni][q] = 0.f;

    int lrow = tid >> 2;   // 0..127 (512 threads cover the chunk in one pass)
    int lseg = tid & 3;

    uint4 ra_h, ra_l, rb_h, rb_l;

    // LDG chunk 0
    {
        int c = lseg * 8;
        long ga = (long)(brow + lrow) * K + c;
        long gb = (long)(bn + lrow) * K + c;
        ra_h = *(const uint4*)&Ah[ga];
        ra_l = *(const uint4*)&Al[ga];
        rb_h = *(const uint4*)&Bh[gb];
        rb_l = *(const uint4*)&Bl[gb];
    }
    // STS chunk 0 -> stage 0
    {
        int so = lrow * PITCH + lseg * 8;
        *(uint4*)&sm[0 * SSZ + so] = ra_h;
        *(uint4*)&sm[1 * SSZ + so] = ra_l;
        *(uint4*)&sm[2 * SSZ + so] = rb_h;
        *(uint4*)&sm[3 * SSZ + so] = rb_l;
    }
    __syncthreads();

    int cur = 0;
    for (int kc = 0; kc < K; kc += 32) {
        bool has_next = (kc + 32 < K);
        if (has_next) {
            int c = kc + 32 + lseg * 8;
            long ga = (long)(brow + lrow) * K + c;
            long gb = (long)(bn + lrow) * K + c;
            ra_h = *(const uint4*)&Ah[ga];
            ra_l = *(const uint4*)&Al[ga];
            rb_h = *(const uint4*)&Bh[gb];
            rb_l = *(const uint4*)&Bl[gb];
        }

        const __nv_bfloat16* sAh = sm + (cur * 4 + 0) * SSZ;
        const __nv_bfloat16* sAl = sm + (cur * 4 + 1) * SSZ;
        const __nv_bfloat16* sBh = sm + (cur * 4 + 2) * SSZ;
        const __nv_bfloat16* sBl = sm + (cur * 4 + 3) * SSZ;

        #pragma unroll
        for (int ks = 0; ks < 2; ks++) {
            int kb = ks * 16 + 2 * tg;
            uint32_t bh0[4], bh1[4], bl0[4], bl1[4];
            #pragma unroll
            for (int ni = 0; ni < 4; ni++) {
                int br = (wn + ni * 8 + g) * PITCH;
                bh0[ni] = *(const uint32_t*)&sBh[br + kb];
                bh1[ni] = *(const uint32_t*)&sBh[br + kb + 8];
                bl0[ni] = *(const uint32_t*)&sBl[br + kb];
                bl1[ni] = *(const uint32_t*)&sBl[br + kb + 8];
            }
            #pragma unroll
            for (int mi = 0; mi < 2; mi++) {
                int ar0 = (wm + mi * 16 + g) * PITCH;
                int ar1 = ar0 + 8 * PITCH;
                uint32_t ah0 = *(const uint32_t*)&sAh[ar0 + kb];
                uint32_t ah1 = *(const uint32_t*)&sAh[ar1 + kb];
                uint32_t ah2 = *(const uint32_t*)&sAh[ar0 + kb + 8];
                uint32_t ah3 = *(const uint32_t*)&sAh[ar1 + kb + 8];
                uint32_t al0 = *(const uint32_t*)&sAl[ar0 + kb];
                uint32_t al1 = *(const uint32_t*)&sAl[ar1 + kb];
                uint32_t al2 = *(const uint32_t*)&sAl[ar0 + kb + 8];
                uint32_t al3 = *(const uint32_t*)&sAl[ar1 + kb + 8];
                // product sweep: consecutive MMAs hit different accumulators
                #pragma unroll
                for (int ni = 0; ni < 4; ni++)
                    MMA16816(acc[mi][ni], ah0, ah1, ah2, ah3, bh0[ni], bh1[ni]);
                #pragma unroll
                for (int ni = 0; ni < 4; ni++)
                    MMA16816(acc[mi][ni], ah0, ah1, ah2, ah3, bl0[ni], bl1[ni]);
                #pragma unroll
                for (int ni = 0; ni < 4; ni++)
                    MMA16816(acc[mi][ni], al0, al1, al2, al3, bh0[ni], bh1[ni]);
            }
        }

        if (has_next) {
            int nxt = cur ^ 1;
            int so = lrow * PITCH + lseg * 8;
            *(uint4*)&sm[(nxt * 4 + 0) * SSZ + so] = ra_h;
            *(uint4*)&sm[(nxt * 4 + 1) * SSZ + so] = ra_l;
            *(uint4*)&sm[(nxt * 4 + 2) * SSZ + so] = rb_h;
            *(uint4*)&sm[(nxt * 4 + 3) * SSZ + so] = rb_l;
            __syncthreads();
            cur = nxt;
        }
    }

    #pragma unroll
    for (int mi = 0; mi < 2; mi++) {
        int row = brow + wm + mi * 16 + g;
        #pragma unroll
        for (int ni = 0; ni < 4; ni++) {
            int col = bn + wn + ni * 8 + 2 * tg;
            if (col < N) {
                float b0 = bias ? bias[col] : 0.f;
                float b1 = bias ? bias[col + 1] : 0.f;
                *(float2*)&C[(long)row * N + col] =
                    make_float2(acc[mi][ni][0] + b0, acc[mi][ni][1] + b1);
                *(float2*)&C[(long)(row + 8) * N + col] =
                    make_float2(acc[mi][ni][2] + b0, acc[mi][ni][3] + b1);
            }
        }
    }
}

// ---------------------------------------------------------------------------
// k_attn: fused attention; 16 rows per block.
// ---------------------------------------------------------------------------
#define ROWS_PER_BLK 16

__global__ __launch_bounds__(256) void k_attn(const float* __restrict__ w3,
                                              const float* __restrict__ bias) {
    __shared__ float fb[S2 * DA];
    __shared__ float es[DA];
    __shared__ float w3s[DA];
    __shared__ float bs[DA];
    __shared__ float sc[S2];
    __shared__ float inv_s;

    int tid = threadIdx.x;
    int b = blockIdx.x, s0 = blockIdx.y * ROWS_PER_BLK;
    int warp = tid >> 5, lane = tid & 31;

    w3s[tid] = w3[tid];
    bs[tid] = bias[tid];
    __syncthreads();
    for (int i = tid; i < S2 * DA; i += 256)
        fb[i] = g_f[b * S2 * DA + i] + bs[i & (DA - 1)];

    for (int r = 0; r < ROWS_PER_BLK; r++) {
        int s = s0 + r;
        __syncthreads();
        es[tid] = g_e[((long)b * S1 + s) * DA + tid];
        __syncthreads();

        #pragma unroll
        for (int tt = 0; tt < 5; tt++) {
            int t = warp + 8 * tt;
            float p = 0.f;
            #pragma unroll
            for (int j = 0; j < 8; j++) {
                int a = lane + 32 * j;
                p += fast_tanh(es[a] + fb[t * DA + a]) * w3s[a];
            }
            #pragma unroll
            for (int off = 16; off; off >>= 1)
                p += __shfl_xor_sync(0xffffffffu, p, off);
            if (lane == 0) sc[t] = p;
        }
        __syncthreads();

        if (warp == 0) {
            float v0 = sc[lane];
            float v1 = (lane + 32 < S2) ? sc[lane + 32] : -3.4e38f;
            float m = fmaxf(v0, v1);
            #pragma unroll
            for (int off = 16; off; off >>= 1)
                m = fmaxf(m, __shfl_xor_sync(0xffffffffu, m, off));
            float e0 = __expf(v0 - m);
            float e1 = (lane + 32 < S2) ? __expf(v1 - m) : 0.f;
            float su = e0 + e1;
            #pragma unroll
            for (int off = 16; off; off >>= 1)
                su += __shfl_xor_sync(0xffffffffu, su, off);
            sc[lane] = e0;
            if (lane + 32 < S2) sc[lane + 32] = e1;
            if (lane == 0) inv_s = 1.f / su;
        }
        __syncthreads();

        float acc = 0.f;
        #pragma unroll 8
        for (int t = 0; t < S2; t++)
            acc += sc[t] * fb[t * DA + tid];
        float ta = acc * inv_s - bs[tid];
        float ev = es[tid];

        long go = ((long)b * S1 + s) * (4 * DA) + tid;
        float vals[4] = {fast_tanh(ev), fast_tanh(ta),
                         fast_tanh(ev * ta), fast_tanh(ev - ta)};
        #pragma unroll
        for (int q = 0; q < 4; q++) {
            __nv_bfloat16 h = __float2bfloat16(vals[q]);
            g_gh[go + q * DA] = h;
            g_gl[go + q * DA] = __float2bfloat16(vals[q] - __bfloat162float(h));
        }
    }
}

// ---------------------------------------------------------------------------
extern "C" void kernel_launch(void* const* d_in, const int* in_sizes, int n_in,
                              void* d_out, int out_size) {
    const float* video = (const float*)d_in[0];
    const float* text  = (const float*)d_in[1];
    const float* w1    = (const float*)d_in[2];
    const float* w2    = (const float*)d_in[3];
    const float* w3    = (const float*)d_in[4];
    const float* bias  = (const float*)d_in[5];
    const float* w4    = (const float*)d_in[6];
    const float* b4    = (const float*)d_in[7];
    float* out = (float*)d_out;

    float* pe;
    __nv_bfloat16 *pvh, *pvl, *pgh, *pgl, *p1h, *p1l, *p4h, *p4l;
    cudaGetSymbolAddress((void**)&pe, g_e);
    cudaGetSymbolAddress((void**)&pvh, g_vh);
    cudaGetSymbolAddress((void**)&pvl, g_vl);
    cudaGetSymbolAddress((void**)&pgh, g_gh);
    cudaGetSymbolAddress((void**)&pgl, g_gl);
    cudaGetSymbolAddress((void**)&p1h, g_w1h);
    cudaGetSymbolAddress((void**)&p1l, g_w1l);
    cudaGetSymbolAddress((void**)&p4h, g_w4h);
    cudaGetSymbolAddress((void**)&p4l, g_w4l);

    cudaFuncSetAttribute(k_gemm_mma, cudaFuncAttributeMaxDynamicSharedMemorySize,
                         GSMEM);

    // fused prologue
    k_pre<<<NBLK_W1 + NBLK_W4 + NBLK_V + NBLK_T, 256>>>(w1, w4, video, text, w2);
    // e = video @ w1  (8192x256, K=1024)
    k_gemm_mma<<<dim3((NB * S1) / 128, DA / 128), 512, GSMEM>>>(
        pvh, pvl, p1h, p1l, nullptr, pe, DA, DV);
    // fused attention -> g (split bf16)
    k_attn<<<dim3(NB, S1 / ROWS_PER_BLK), 256>>>(w3, bias);
    // out = g @ w4 + b4  (8192x500, K=1024)
    k_gemm_mma<<<dim3((NB * S1) / 128, DO_PAD / 128), 512, GSMEM>>>(
        pgh, pgl, p4h, p4l, b4, out, DO, 4 * DA);
}